// round 16
// baseline (speedup 1.0000x reference)
#include <cuda_runtime.h>
#include <math.h>

// bs=4096, nt=2048. Output depends only on the LAST batch row:
//   S    = sum_j [ (y-mu)^2/sigma + log(sigma) ]   over row (bs-1)
//   loss = 0.5 * (S + nt*log(2*pi)) / (nt*bs)
// Single-block latency-floor reduction over 24 KiB.
// R15 = R13 (measured-best: flat STS tail, ncu 3.776us, wall 4.61us) +
//   log2-domain accumulation: per-thread term is
//       num * rcp(P) * (1/ln2) + lg2(P)
//   (the 1/ln2 folds into the parallel fma tree), and the final sum is
//   scaled by ln2 once — removing the dependent FMUL after MUFU.LG2 from
//   every thread's critical path.
// History: redux.f32 unsupported on sm_103; lane0-serial tail slower;
//   bar.arrive asymmetric barrier neutral; 512t > {256t, 1024t}.

#define BS 4096
#define NT 2048
#define LOG_2PI 1.8378770664093453f
#define INV_LN2 1.4426950408889634f   // 1/ln(2)
#define LN2     0.6931471805599453f

__global__ __launch_bounds__(512, 1)
void criterion_lastrow_kernel(const float4* __restrict__ mu,
                              const float4* __restrict__ sigma,
                              const float4* __restrict__ target_y,
                              float* __restrict__ out) {
    const int tid = threadIdx.x;   // 0..511, each handles 4 floats

    __shared__ float partials[512];

    // 3 coalesced LDG.128, issued at kernel entry (offset folded on host).
    const float4 s = sigma[tid];     // sigma first: MUFUs depend only on it
    const float4 m = mu[tid];
    const float4 y = target_y[tid];

    const float p01 = s.x * s.y;
    const float p23 = s.z * s.w;
    const float P   = p01 * p23;
    const float r   = __frcp_rn(P);    // MUFU.RCP
    const float lg2 = __log2f(P);      // bare MUFU.LG2, no trailing FMUL

    const float d0 = y.x - m.x;
    const float d1 = y.y - m.y;
    const float d2 = y.z - m.z;
    const float d3 = y.w - m.w;

    // num scaled by 1/ln2 inside the (parallel) fma tree.
    const float t01 = fmaf(d0 * d0, s.y, d1 * d1 * s.x);
    const float t23 = fmaf(d2 * d2, s.w, d3 * d3 * s.z);
    const float num = fmaf(t01, p23 * INV_LN2, t23 * (p01 * INV_LN2));

    // Per-thread partial (log2 domain) straight to smem.
    partials[tid] = fmaf(num, r, lg2);
    __syncthreads();

    if (tid < 32) {
        // Each lane sums 16 partials: 4 x LDS.128, pipelined.
        const float4* p4 = reinterpret_cast<const float4*>(partials);
        const float4 a = p4[tid * 4 + 0];
        const float4 b = p4[tid * 4 + 1];
        const float4 c = p4[tid * 4 + 2];
        const float4 e = p4[tid * 4 + 3];

        float v = ((a.x + a.y) + (a.z + a.w))
                + ((b.x + b.y) + (b.z + b.w))
                + ((c.x + c.y) + (c.z + c.w))
                + ((e.x + e.y) + (e.z + e.w));

        #pragma unroll
        for (int off = 16; off > 0; off >>= 1)
            v += __shfl_xor_sync(0xFFFFFFFFu, v, off);

        if (tid == 0) {
            // Convert back from log2 domain (x ln2) and apply 0.5/(NT*BS),
            // both folded into one constant.
            const float scale = 0.5f * LN2 / ((float)NT * (float)BS);
            out[0] = fmaf(v, scale,
                          0.5f * (float)NT * LOG_2PI / ((float)NT * (float)BS));
        }
    }
}

extern "C" void kernel_launch(void* const* d_in, const int* in_sizes, int n_in,
                              void* d_out, int out_size) {
    const long long base = (long long)(BS - 1) * NT;  // fold offset on host
    const float4* mu       = (const float4*)((const float*)d_in[0] + base);
    const float4* sigma    = (const float4*)((const float*)d_in[1] + base);
    const float4* target_y = (const float4*)((const float*)d_in[2] + base);
    criterion_lastrow_kernel<<<1, 512>>>(mu, sigma, target_y, (float*)d_out);
}

// round 17
// speedup vs baseline: 1.0539x; 1.0539x over previous
#include <cuda_runtime.h>
#include <math.h>

// bs=4096, nt=2048. Output depends only on the LAST batch row:
//   S    = sum_j [ (y-mu)^2/sigma + log(sigma) ]   over row (bs-1)
//   loss = 0.5 * (S + nt*log(2*pi)) / (nt*bs)
// Single-block latency-floor reduction over 24 KiB.
//
// FINAL (= R13, twice-reproduced best: ncu 3.776/3.808us, wall 4.61us):
//   - 512 threads, 3x LDG.128/thread, row offset folded on host
//   - fused body: 1 MUFU.RCP + 1 MUFU.LG2 per thread (common denominator
//     P = s0 s1 s2 s3 shared by the divide and the log), MUFUs hoisted to
//     depend only on sigma, balanced fma tree for the numerator
//   - flat tail: bare STS -> BAR -> warp0 4xLDS.128 fold -> 5-shuffle
//     butterfly
// Measured dead ends: redux.f32 (not on sm_103), lane0-serial tail (+0.2us),
//   asymmetric bar.arrive (+0.15us), log2-domain accum (noise), 256t/1024t
//   (slower), per-element div/log (+0.4us).

#define BS 4096
#define NT 2048
#define LOG_2PI 1.8378770664093453f

__global__ __launch_bounds__(512, 1)
void criterion_lastrow_kernel(const float4* __restrict__ mu,
                              const float4* __restrict__ sigma,
                              const float4* __restrict__ target_y,
                              float* __restrict__ out) {
    const int tid = threadIdx.x;   // 0..511, each handles 4 floats

    __shared__ float partials[512];

    // 3 coalesced LDG.128, issued at kernel entry (offset folded on host).
    const float4 s = sigma[tid];     // sigma first: MUFUs depend only on it
    const float4 m = mu[tid];
    const float4 y = target_y[tid];

    const float p01 = s.x * s.y;
    const float p23 = s.z * s.w;
    const float P   = p01 * p23;
    const float r   = __frcp_rn(P);   // MUFU.RCP
    const float lg  = __logf(P);      // MUFU.LG2

    const float d0 = y.x - m.x;
    const float d1 = y.y - m.y;
    const float d2 = y.z - m.z;
    const float d3 = y.w - m.w;

    const float t01 = fmaf(d0 * d0, s.y, d1 * d1 * s.x);
    const float t23 = fmaf(d2 * d2, s.w, d3 * d3 * s.z);
    const float num = fmaf(t01, p23, t23 * p01);

    // Per-thread partial straight to smem — no pre-barrier shuffles.
    partials[tid] = fmaf(num, r, lg);
    __syncthreads();

    if (tid < 32) {
        // Each lane sums 16 partials: 4 x LDS.128, pipelined.
        const float4* p4 = reinterpret_cast<const float4*>(partials);
        const float4 a = p4[tid * 4 + 0];
        const float4 b = p4[tid * 4 + 1];
        const float4 c = p4[tid * 4 + 2];
        const float4 e = p4[tid * 4 + 3];

        float v = ((a.x + a.y) + (a.z + a.w))
                + ((b.x + b.y) + (b.z + b.w))
                + ((c.x + c.y) + (c.z + c.w))
                + ((e.x + e.y) + (e.z + e.w));

        #pragma unroll
        for (int off = 16; off > 0; off >>= 1)
            v += __shfl_xor_sync(0xFFFFFFFFu, v, off);

        if (tid == 0) {
            const float scale = 0.5f / ((float)NT * (float)BS);
            out[0] = (v + (float)NT * LOG_2PI) * scale;
        }
    }
}

extern "C" void kernel_launch(void* const* d_in, const int* in_sizes, int n_in,
                              void* d_out, int out_size) {
    const long long base = (long long)(BS - 1) * NT;  // fold offset on host
    const float4* mu       = (const float4*)((const float*)d_in[0] + base);
    const float4* sigma    = (const float4*)((const float*)d_in[1] + base);
    const float4* target_y = (const float4*)((const float*)d_in[2] + base);
    criterion_lastrow_kernel<<<1, 512>>>(mu, sigma, target_y, (float*)d_out);
}